// round 2
// baseline (speedup 1.0000x reference)
#include <cuda_runtime.h>
#include <cuda_bf16.h>

// Problem constants (fixed by the reference)
#define BB 32
#define NN 64
#define EE 4032      // N*(N-1)
#define EPN 63       // edges per receiver node
#define HH 256
#define OO 256
#define FI 4
#define NSTEP 10

// ---------------- scratch (device globals; no allocation allowed) ----------
__device__ float g_xst[BB * NN * FI];    // current state x
__device__ float g_xarg[BB * NN * FI];   // argument to f for current stage
__device__ float g_kacc[BB * NN * FI];   // RK4 accumulator
__device__ float g_agg[BB * NN * OO];    // per-node aggregated messages

// ---------------- init: x0 = inputs[:, :, t=0, :] ---------------------------
__global__ void init_kernel(const float* __restrict__ inputs)
{
    int i = blockIdx.x * blockDim.x + threadIdx.x;  // over B*N*4 = 8192
    if (i < BB * NN * FI) {
        int f = i & 3;
        int row = i >> 2;                 // b*64+n
        float v = inputs[row * (11 * FI) + f];  // inputs[b][n][0][f], T=11
        g_xst[i] = v;
        g_xarg[i] = v;
    }
}

// ---------------- edge kernel: per (b, receiver n) ---------------------------
// Computes agg[b,n,:] = sum_{el<63} sum_k edges[b,e,k] *
//                       relu( relu(pre[e] @ W1[k] + b1[k]) @ W2[k] + b2[k] )
// Dynamic smem layout (floats):
//   s_hT  [256][64]  : h transposed (hidden, edge), per-k
//   s_preT[8][64]    : pre transposed
//   s_ew  [2][64]    : edge weights
//   s_W1  [8][256]   : W1 slice for current k
#define EDGE_SMEM_FLOATS (256*64 + 8*64 + 2*64 + 8*256)

__global__ __launch_bounds__(256) void edge_kernel(
    const float* __restrict__ edges,   // [B][E][2]
    const float* __restrict__ W1,      // [2][8][256]
    const float* __restrict__ b1,      // [2][256]
    const float* __restrict__ W2,      // [2][256][256]
    const float* __restrict__ b2)      // [2][256]
{
    extern __shared__ float smem[];
    float* s_hT   = smem;                    // 16384
    float* s_preT = smem + 16384;            // 512
    float* s_ew   = s_preT + 512;            // 128
    float* s_W1   = s_ew + 128;              // 2048

    int b = blockIdx.x >> 6;
    int n = blockIdx.x & 63;
    int t = threadIdx.x;

    // gather pre = [x_send, x_recv] and edge weights
    if (t < 64) {
        int el = t;
        float4 xs = make_float4(0.f, 0.f, 0.f, 0.f), xr = xs;
        float2 ew = make_float2(0.f, 0.f);
        if (el < EPN) {
            int send = (el < n) ? el : el + 1;
            xs = *(const float4*)(g_xarg + (b * NN + send) * 4);
            xr = *(const float4*)(g_xarg + (b * NN + n) * 4);
            ew = *(const float2*)(edges + ((long)(b * EE) + n * EPN + el) * 2);
        }
        s_preT[0 * 64 + el] = xs.x; s_preT[1 * 64 + el] = xs.y;
        s_preT[2 * 64 + el] = xs.z; s_preT[3 * 64 + el] = xs.w;
        s_preT[4 * 64 + el] = xr.x; s_preT[5 * 64 + el] = xr.y;
        s_preT[6 * 64 + el] = xr.z; s_preT[7 * 64 + el] = xr.w;
        s_ew[0 * 64 + el] = ew.x; s_ew[1 * 64 + el] = ew.y;
    }

    float aggv = 0.0f;

    for (int k = 0; k < 2; k++) {
        __syncthreads();   // protects preT (k=0) and s_hT/s_W1 reuse (k=1)

        // stage W1[k] into shared
        #pragma unroll
        for (int i = 0; i < 8; i++) {
            int idx = i * 256 + t;
            s_W1[idx] = W1[k * 2048 + idx];
        }
        __syncthreads();

        // compute hT[hh][el] = relu(b1 + sum_f pre[f][el]*W1[f][hh])
        {
            int el = t & 63;
            int hb = t >> 6;           // 0..3
            float pr[8];
            #pragma unroll
            for (int f = 0; f < 8; f++) pr[f] = s_preT[f * 64 + el];
            #pragma unroll 8
            for (int iter = 0; iter < 64; iter++) {
                int hh = hb * 64 + iter;
                float acc = b1[k * 256 + hh];
                #pragma unroll
                for (int f = 0; f < 8; f++) acc += pr[f] * s_W1[f * 256 + hh];
                s_hT[hh * 64 + el] = fmaxf(acc, 0.f);
            }
        }
        __syncthreads();

        // GEMM: thread t owns output column o=t, all 64 (63 real) edges
        float acc[64];
        #pragma unroll
        for (int e2 = 0; e2 < 64; e2++) acc[e2] = 0.f;

        const float* w2c = W2 + k * 65536 + t;   // column t, row stride 256
        #pragma unroll 2
        for (int j = 0; j < 256; j++) {
            float w = __ldg(w2c + j * 256);
            const float4* hrow = (const float4*)(s_hT + j * 64);
            #pragma unroll
            for (int q = 0; q < 16; q++) {
                float4 hv = hrow[q];
                acc[4 * q + 0] += hv.x * w;
                acc[4 * q + 1] += hv.y * w;
                acc[4 * q + 2] += hv.z * w;
                acc[4 * q + 3] += hv.w * w;
            }
        }
        float bias = b2[k * 256 + t];
        #pragma unroll
        for (int e2 = 0; e2 < EPN; e2++) {
            aggv += s_ew[k * 64 + e2] * fmaxf(acc[e2] + bias, 0.f);
        }
    }

    g_agg[(b * NN + n) * OO + t] = aggv;
}

// ---------------- node kernel: output MLP + RK4 bookkeeping ------------------
// 8 rows (b,n) per block; thread t owns hidden/output column t.
__global__ __launch_bounds__(256) void node_kernel(
    const float* __restrict__ Wo1, const float* __restrict__ bo1,   // [260][256],[256]
    const float* __restrict__ Wo2, const float* __restrict__ bo2,   // [256][256],[256]
    const float* __restrict__ Wo3, const float* __restrict__ bo3,   // [256][4],[4]
    float* __restrict__ outp,                                        // [B][N][10][4]
    int stage, int step)
{
    __shared__ float s_aug[8][260];
    __shared__ float s_h[8][256];
    __shared__ float s_h2[8][256];

    int r0 = blockIdx.x * 8;   // row = b*64+n
    int t = threadIdx.x;

    for (int i = t; i < 8 * 260; i += 256) {
        int r = i / 260, c = i % 260;
        int row = r0 + r;
        s_aug[r][c] = (c < 4) ? g_xarg[row * 4 + c] : g_agg[row * 256 + (c - 4)];
    }
    __syncthreads();

    float acc[8];
    {
        float bv = bo1[t];
        #pragma unroll
        for (int r = 0; r < 8; r++) acc[r] = bv;
    }
    for (int j = 0; j < 260; j++) {
        float w = Wo1[j * 256 + t];
        #pragma unroll
        for (int r = 0; r < 8; r++) acc[r] += s_aug[r][j] * w;
    }
    #pragma unroll
    for (int r = 0; r < 8; r++) s_h[r][t] = fmaxf(acc[r], 0.f);
    __syncthreads();

    {
        float bv = bo2[t];
        #pragma unroll
        for (int r = 0; r < 8; r++) acc[r] = bv;
    }
    for (int j = 0; j < 256; j++) {
        float w = Wo2[j * 256 + t];
        #pragma unroll
        for (int r = 0; r < 8; r++) acc[r] += s_h[r][j] * w;
    }
    __syncthreads();
    #pragma unroll
    for (int r = 0; r < 8; r++) s_h2[r][t] = fmaxf(acc[r], 0.f);
    __syncthreads();

    // final 256->4 projection: warp w handles row w
    int wr = t >> 5, lane = t & 31;
    float4 pf = make_float4(0.f, 0.f, 0.f, 0.f);
    for (int j = lane; j < 256; j += 32) {
        float v = s_h2[wr][j];
        float4 w3 = *(const float4*)(Wo3 + j * 4);
        pf.x += v * w3.x; pf.y += v * w3.y;
        pf.z += v * w3.z; pf.w += v * w3.w;
    }
    #pragma unroll
    for (int off = 16; off; off >>= 1) {
        pf.x += __shfl_xor_sync(0xffffffffu, pf.x, off);
        pf.y += __shfl_xor_sync(0xffffffffu, pf.y, off);
        pf.z += __shfl_xor_sync(0xffffffffu, pf.z, off);
        pf.w += __shfl_xor_sync(0xffffffffu, pf.w, off);
    }

    if (lane == 0) {
        int row = r0 + wr;
        // dt exactly as jnp computes it in fp32: t[s] = float(s)/10
        float dt = (float)(step + 1) / 10.0f - (float)step / 10.0f;

        float4 xa = *(const float4*)(g_xarg + row * 4);
        float4 xs = *(const float4*)(g_xst + row * 4);

        float4 ko;   // k_i = f(xarg) = xarg + p
        ko.x = xa.x + pf.x + bo3[0];
        ko.y = xa.y + pf.y + bo3[1];
        ko.z = xa.z + pf.z + bo3[2];
        ko.w = xa.w + pf.w + bo3[3];

        float4 ka;
        if (stage == 0) {
            ka = ko;
        } else {
            ka = *(const float4*)(g_kacc + row * 4);
            float s = (stage == 3) ? 1.0f : 2.0f;
            ka.x += s * ko.x; ka.y += s * ko.y;
            ka.z += s * ko.z; ka.w += s * ko.w;
        }

        if (stage < 3) {
            *(float4*)(g_kacc + row * 4) = ka;
            float c = (stage == 2) ? dt : 0.5f * dt;
            float4 xn;
            xn.x = xs.x + c * ko.x; xn.y = xs.y + c * ko.y;
            xn.z = xs.z + c * ko.z; xn.w = xs.w + c * ko.w;
            *(float4*)(g_xarg + row * 4) = xn;
        } else {
            float c = dt * (1.0f / 6.0f);
            float4 xn;
            xn.x = xs.x + c * ka.x; xn.y = xs.y + c * ka.y;
            xn.z = xs.z + c * ka.z; xn.w = xs.w + c * ka.w;
            *(float4*)(g_xst + row * 4) = xn;
            *(float4*)(g_xarg + row * 4) = xn;
            *(float4*)(outp + (row * NSTEP + step) * 4) = xn;
        }
    }
}

// ---------------- launch ------------------------------------------------------
extern "C" void kernel_launch(void* const* d_in, const int* in_sizes, int n_in,
                              void* d_out, int out_size)
{
    const float* inputs = (const float*)d_in[0];   // (B,N,T,F)
    const float* edges  = (const float*)d_in[1];   // (B,E,K)
    // d_in[2] rel_rec, d_in[3] rel_send : structure known, unused
    const float* W1  = (const float*)d_in[4];
    const float* b1  = (const float*)d_in[5];
    const float* W2  = (const float*)d_in[6];
    const float* b2  = (const float*)d_in[7];
    const float* Wo1 = (const float*)d_in[8];
    const float* bo1 = (const float*)d_in[9];
    const float* Wo2 = (const float*)d_in[10];
    const float* bo2 = (const float*)d_in[11];
    const float* Wo3 = (const float*)d_in[12];
    const float* bo3 = (const float*)d_in[13];
    float* outp = (float*)d_out;                   // (B,N,10,F)

    static const size_t edge_smem = EDGE_SMEM_FLOATS * sizeof(float);
    cudaFuncSetAttribute(edge_kernel,
                         cudaFuncAttributeMaxDynamicSharedMemorySize,
                         (int)edge_smem);

    init_kernel<<<(BB * NN * FI + 255) / 256, 256>>>(inputs);

    for (int step = 0; step < NSTEP; step++) {
        for (int stage = 0; stage < 4; stage++) {
            edge_kernel<<<BB * NN, 256, edge_smem>>>(edges, W1, b1, W2, b2);
            node_kernel<<<BB * NN / 8, 256>>>(Wo1, bo1, Wo2, bo2, Wo3, bo3,
                                              outp, stage, step);
        }
    }
}

// round 5
// speedup vs baseline: 1.9192x; 1.9192x over previous
#include <cuda_runtime.h>
#include <cuda_bf16.h>
#include <cstdint>

// Problem constants
#define BB 32
#define NN 64
#define EE 4032
#define EPN 63
#define FI 4
#define NSTEP 10

// ---------------- scratch (device globals) ----------------------------------
__device__ float g_xst[BB * NN * FI];
__device__ float g_xarg[BB * NN * FI];
__device__ float g_kacc[BB * NN * FI];
__device__ float g_agg[BB * NN * 256];
__device__ float g_w2hi[2 * 256 * 256];   // tf32-high part of W2
__device__ float g_w2lo[2 * 256 * 256];   // residual  part of W2

// ---------------- smem layout (bytes) ----------------------------------------
#define SM_PRE   0        // 128 x 8 f32             (4096)
#define SM_EW    4096     // 128 x 2 f32             (1024)
#define SM_B1    5120     // 2 x 256 f32             (2048)
#define SM_B2    7168     // 2 x 256 f32             (2048)
#define SM_W1    9216     // 2 x 8 x 256 f32         (16384)
#define SM_PART  25600    // 2 x 4 x 256 f32         (8192)
#define SM_H     33792    // 2 bufs x 128 x 36 f32   (36864)
#define SM_W2    70656    // 2 bufs x {hi,lo} x 32 x 264 f32 (135168)
#define SMEM_TOT 205824

#define HB_STRIDE 36
#define WB_STRIDE 264
#define HBUF_FLOATS (128 * HB_STRIDE)     // 4608
#define WBUF_FLOATS (32 * WB_STRIDE)      // 8448

// ---------------- PTX helpers -------------------------------------------------
__device__ __forceinline__ uint32_t smem_u32(const void* p) {
    uint32_t a;
    asm("{ .reg .u64 t; cvta.to.shared.u64 t, %1; cvt.u32.u64 %0, t; }"
        : "=r"(a) : "l"(p));
    return a;
}
#define CP_ASYNC16(dst, src) \
    asm volatile("cp.async.cg.shared.global [%0], [%1], 16;" :: "r"(dst), "l"(src))
#define CP_COMMIT() asm volatile("cp.async.commit_group;" ::: "memory")
#define CP_WAIT1()  asm volatile("cp.async.wait_group 1;" ::: "memory")
#define CP_WAIT0()  asm volatile("cp.async.wait_group 0;" ::: "memory")

#define MMA_TF32(d, a, b0, b1)                                              \
    asm volatile("mma.sync.aligned.m16n8k8.row.col.f32.tf32.tf32.f32 "      \
        "{%0,%1,%2,%3}, {%4,%5,%6,%7}, {%8,%9}, {%0,%1,%2,%3};"             \
        : "+f"((d)[0]), "+f"((d)[1]), "+f"((d)[2]), "+f"((d)[3])            \
        : "r"((a)[0]), "r"((a)[1]), "r"((a)[2]), "r"((a)[3]),               \
          "r"(b0), "r"(b1))

__device__ __forceinline__ uint32_t tf32_hi(float x) {
    uint32_t h;
    asm("cvt.rna.tf32.f32 %0, %1;" : "=r"(h) : "f"(x));
    return h;
}

// ---------------- init ----------------------------------------------------------
__global__ void init_kernel(const float* __restrict__ inputs)
{
    int i = blockIdx.x * blockDim.x + threadIdx.x;
    if (i < BB * NN * FI) {
        int f = i & 3;
        int row = i >> 2;
        float v = inputs[row * (11 * FI) + f];
        g_xst[i] = v;
        g_xarg[i] = v;
    }
}

// split W2 into tf32 hi + fp32 residual (once per launch; W2 is constant)
__global__ void w2split_kernel(const float* __restrict__ W2)
{
    int i = blockIdx.x * blockDim.x + threadIdx.x;   // 131072 total
    float w = W2[i];
    uint32_t h = tf32_hi(w);
    float hf = __uint_as_float(h);
    g_w2hi[i] = hf;
    g_w2lo[i] = w - hf;
}

// ---------------- edge kernel: mma.sync 3xTF32 -----------------------------------
// CTA = (batch, 2 receivers). M=128 edge rows (2x64; rows 63/127 padded ew=0),
// N=256 outputs, K=256 hidden (x2 k-components), in 16 chunks of 32.
__global__ __launch_bounds__(256, 1) void edge_mma_kernel(
    const float* __restrict__ edges,
    const float* __restrict__ W1g, const float* __restrict__ b1g,
    const float* __restrict__ b2g)
{
    extern __shared__ float s[];
    uint32_t sb = smem_u32(s);
    const int t = threadIdx.x;
    const int wid = t >> 5, lane = t & 31;
    const int group = lane >> 2, tid4 = lane & 3;
    const int wm = wid & 3, wn = wid >> 2;          // 4 M-warps x 2 N-warps
    const int b = blockIdx.x >> 5;
    const int n0 = (blockIdx.x & 31) * 2;

    // ---- stage constants
    for (int i = t; i < 512; i += 256) {
        s[SM_B1 / 4 + i] = b1g[i];
        s[SM_B2 / 4 + i] = b2g[i];
    }
    for (int i = t; i < 4096; i += 256) s[SM_W1 / 4 + i] = W1g[i];
    if (t < 128) {
        int g = t >> 6, n = n0 + g, el = t & 63;
        float4 xs = make_float4(0.f, 0.f, 0.f, 0.f), xr = xs;
        float2 ew = make_float2(0.f, 0.f);
        if (el < EPN) {
            int send = (el < n) ? el : el + 1;
            xs = *(const float4*)(g_xarg + (b * NN + send) * 4);
            xr = *(const float4*)(g_xarg + (b * NN + n) * 4);
            ew = *(const float2*)(edges + ((long)(b * EE) + n * EPN + el) * 2);
        }
        float4* pr = (float4*)(s + SM_PRE / 4 + t * 8);
        pr[0] = xs; pr[1] = xr;
        s[SM_EW / 4 + t * 2 + 0] = ew.x;
        s[SM_EW / 4 + t * 2 + 1] = ew.y;
    }
    __syncthreads();

    // ---- staging helpers
    auto stage_w2 = [&](int c, int buf) {
        int k = c >> 3, ck = c & 7;
        size_t off = (size_t)(k * 256 + ck * 32) * 256;
        const float* srch = g_w2hi + off;
        const float* srcl = g_w2lo + off;
        uint32_t dbh = sb + SM_W2 + (uint32_t)buf * (2u * WBUF_FLOATS * 4u);
        uint32_t dbl = dbh + WBUF_FLOATS * 4u;
        #pragma unroll
        for (int i = 0; i < 8; i++) {
            int idx = t + i * 256;            // float4 index, 2048 total
            int row = idx >> 6, c4 = idx & 63;
            uint32_t doff = (uint32_t)(row * WB_STRIDE + c4 * 4) * 4;
            CP_ASYNC16(dbh + doff, srch + row * 256 + c4 * 4);
            CP_ASYNC16(dbl + doff, srcl + row * 256 + c4 * 4);
        }
    };
    auto compute_h = [&](int c, int buf) {
        int k = c >> 3, ck = c & 7;
        int jl = t & 31, rg = t >> 5;
        float w1v[8];
        #pragma unroll
        for (int f = 0; f < 8; f++)
            w1v[f] = s[SM_W1 / 4 + (k * 8 + f) * 256 + ck * 32 + jl];
        float b1v = s[SM_B1 / 4 + k * 256 + ck * 32 + jl];
        float* hb = s + SM_H / 4 + buf * HBUF_FLOATS;
        #pragma unroll
        for (int rr = 0; rr < 16; rr++) {
            int r = rg * 16 + rr;
            const float4* pr = (const float4*)(s + SM_PRE / 4 + r * 8);
            float4 p0 = pr[0], p1 = pr[1];
            float acc = b1v;
            acc += p0.x * w1v[0]; acc += p0.y * w1v[1];
            acc += p0.z * w1v[2]; acc += p0.w * w1v[3];
            acc += p1.x * w1v[4]; acc += p1.y * w1v[5];
            acc += p1.z * w1v[6]; acc += p1.w * w1v[7];
            hb[r * HB_STRIDE + jl] = fmaxf(acc, 0.f);
        }
    };

    float acc[2][16][4];
    #pragma unroll
    for (int m = 0; m < 2; m++)
        #pragma unroll
        for (int nt = 0; nt < 16; nt++)
            #pragma unroll
            for (int q = 0; q < 4; q++) acc[m][nt][q] = 0.f;

    // prologue: chunk 0
    stage_w2(0, 0);
    CP_COMMIT();
    compute_h(0, 0);

    for (int c = 0; c < 16; c++) {
        int buf = c & 1;
        if (c < 15) {
            stage_w2(c + 1, 1 - buf);
            CP_COMMIT();
            compute_h(c + 1, 1 - buf);
            CP_WAIT1();
        } else {
            CP_WAIT0();
        }
        __syncthreads();

        // ---- 3xTF32 mma over chunk c
        {
            const float* hb  = s + SM_H / 4 + buf * HBUF_FLOATS + (wm * 32) * HB_STRIDE;
            const float* wbh = s + SM_W2 / 4 + buf * (2 * WBUF_FLOATS) + wn * 128;
            #pragma unroll
            for (int ks = 0; ks < 4; ks++) {
                uint32_t ah[2][4], al[2][4];
                int col = ks * 8 + tid4;
                #pragma unroll
                for (int m = 0; m < 2; m++) {
                    int r0 = m * 16 + group;
                    float v0 = hb[(r0)     * HB_STRIDE + col];
                    float v1 = hb[(r0 + 8) * HB_STRIDE + col];
                    float v2 = hb[(r0)     * HB_STRIDE + col + 4];
                    float v3 = hb[(r0 + 8) * HB_STRIDE + col + 4];
                    ah[m][0] = tf32_hi(v0); al[m][0] = __float_as_uint(v0 - __uint_as_float(ah[m][0]));
                    ah[m][1] = tf32_hi(v1); al[m][1] = __float_as_uint(v1 - __uint_as_float(ah[m][1]));
                    ah[m][2] = tf32_hi(v2); al[m][2] = __float_as_uint(v2 - __uint_as_float(ah[m][2]));
                    ah[m][3] = tf32_hi(v3); al[m][3] = __float_as_uint(v3 - __uint_as_float(ah[m][3]));
                }
                const float* w0h = wbh + (ks * 8 + tid4) * WB_STRIDE + group;
                const float* w1h = w0h + 4 * WB_STRIDE;
                const float* w0l = w0h + WBUF_FLOATS;
                const float* w1l = w1h + WBUF_FLOATS;
                #pragma unroll
                for (int nt = 0; nt < 16; nt++) {
                    uint32_t b0h = __float_as_uint(w0h[nt * 8]);
                    uint32_t b1h = __float_as_uint(w1h[nt * 8]);
                    uint32_t b0l = __float_as_uint(w0l[nt * 8]);
                    uint32_t b1l = __float_as_uint(w1l[nt * 8]);
                    MMA_TF32(acc[0][nt], ah[0], b0h, b1h);
                    MMA_TF32(acc[1][nt], ah[1], b0h, b1h);
                    MMA_TF32(acc[0][nt], al[0], b0h, b1h);
                    MMA_TF32(acc[1][nt], al[1], b0h, b1h);
                    MMA_TF32(acc[0][nt], ah[0], b0l, b1l);
                    MMA_TF32(acc[1][nt], ah[1], b0l, b1l);
                }
            }
        }

        // ---- epilogue for this k-component after its last chunk
        if ((c & 7) == 7) {
            int k = c >> 3;
            float colsum[32];
            #pragma unroll
            for (int i = 0; i < 32; i++) colsum[i] = 0.f;
            #pragma unroll
            for (int m = 0; m < 2; m++) {
                int rbase = wm * 32 + m * 16 + group;
                float ew0 = s[SM_EW / 4 + rbase * 2 + k];
                float ew1 = s[SM_EW / 4 + (rbase + 8) * 2 + k];
                #pragma unroll
                for (int nt = 0; nt < 16; nt++) {
                    int col0 = wn * 128 + nt * 8 + tid4 * 2;
                    float bz0 = s[SM_B2 / 4 + k * 256 + col0];
                    float bz1 = s[SM_B2 / 4 + k * 256 + col0 + 1];
                    colsum[nt * 2 + 0] += fmaxf(acc[m][nt][0] + bz0, 0.f) * ew0
                                        + fmaxf(acc[m][nt][2] + bz0, 0.f) * ew1;
                    colsum[nt * 2 + 1] += fmaxf(acc[m][nt][1] + bz1, 0.f) * ew0
                                        + fmaxf(acc[m][nt][3] + bz1, 0.f) * ew1;
                }
            }
            #pragma unroll
            for (int off = 4; off <= 16; off <<= 1)
                #pragma unroll
                for (int i = 0; i < 32; i++)
                    colsum[i] += __shfl_xor_sync(0xffffffffu, colsum[i], off);
            if (lane < 4) {
                float* dst = s + SM_PART / 4 + (k * 4 + wm) * 256 + wn * 128;
                #pragma unroll
                for (int nt = 0; nt < 16; nt++) {
                    dst[nt * 8 + lane * 2 + 0] = colsum[nt * 2 + 0];
                    dst[nt * 8 + lane * 2 + 1] = colsum[nt * 2 + 1];
                }
            }
            #pragma unroll
            for (int m = 0; m < 2; m++)
                #pragma unroll
                for (int nt = 0; nt < 16; nt++)
                    #pragma unroll
                    for (int q = 0; q < 4; q++) acc[m][nt][q] = 0.f;
        }
        __syncthreads();
    }

    // ---- final aggregation across k and M-warps
    {
        const float* p = s + SM_PART / 4;
        float a0 = p[0 * 256 + t] + p[1 * 256 + t] + p[4 * 256 + t] + p[5 * 256 + t];
        float a1 = p[2 * 256 + t] + p[3 * 256 + t] + p[6 * 256 + t] + p[7 * 256 + t];
        g_agg[(b * NN + n0) * 256 + t] = a0;
        g_agg[(b * NN + n0 + 1) * 256 + t] = a1;
    }
}

// ---------------- node kernel: output MLP + RK4 bookkeeping -------------------
__global__ __launch_bounds__(256) void node_kernel(
    const float* __restrict__ Wo1, const float* __restrict__ bo1,
    const float* __restrict__ Wo2, const float* __restrict__ bo2,
    const float* __restrict__ Wo3, const float* __restrict__ bo3,
    float* __restrict__ outp, int stage, int step)
{
    __shared__ float s_aug[8][260];
    __shared__ float s_h[8][256];
    __shared__ float s_h2[8][256];

    int r0 = blockIdx.x * 8;
    int t = threadIdx.x;

    for (int i = t; i < 8 * 260; i += 256) {
        int r = i / 260, c = i % 260;
        int row = r0 + r;
        s_aug[r][c] = (c < 4) ? g_xarg[row * 4 + c] : g_agg[row * 256 + (c - 4)];
    }
    __syncthreads();

    float acc[8];
    {
        float bv = bo1[t];
        #pragma unroll
        for (int r = 0; r < 8; r++) acc[r] = bv;
    }
    for (int j = 0; j < 260; j++) {
        float w = Wo1[j * 256 + t];
        #pragma unroll
        for (int r = 0; r < 8; r++) acc[r] += s_aug[r][j] * w;
    }
    #pragma unroll
    for (int r = 0; r < 8; r++) s_h[r][t] = fmaxf(acc[r], 0.f);
    __syncthreads();

    {
        float bv = bo2[t];
        #pragma unroll
        for (int r = 0; r < 8; r++) acc[r] = bv;
    }
    for (int j = 0; j < 256; j++) {
        float w = Wo2[j * 256 + t];
        #pragma unroll
        for (int r = 0; r < 8; r++) acc[r] += s_h[r][j] * w;
    }
    __syncthreads();
    #pragma unroll
    for (int r = 0; r < 8; r++) s_h2[r][t] = fmaxf(acc[r], 0.f);
    __syncthreads();

    int wr = t >> 5, lane = t & 31;
    float4 pf = make_float4(0.f, 0.f, 0.f, 0.f);
    for (int j = lane; j < 256; j += 32) {
        float v = s_h2[wr][j];
        float4 w3 = *(const float4*)(Wo3 + j * 4);
        pf.x += v * w3.x; pf.y += v * w3.y;
        pf.z += v * w3.z; pf.w += v * w3.w;
    }
    #pragma unroll
    for (int off = 16; off; off >>= 1) {
        pf.x += __shfl_xor_sync(0xffffffffu, pf.x, off);
        pf.y += __shfl_xor_sync(0xffffffffu, pf.y, off);
        pf.z += __shfl_xor_sync(0xffffffffu, pf.z, off);
        pf.w += __shfl_xor_sync(0xffffffffu, pf.w, off);
    }

    if (lane == 0) {
        int row = r0 + wr;
        float dt = (float)(step + 1) / 10.0f - (float)step / 10.0f;

        float4 xa = *(const float4*)(g_xarg + row * 4);
        float4 xs = *(const float4*)(g_xst + row * 4);

        float4 ko;
        ko.x = xa.x + pf.x + bo3[0];
        ko.y = xa.y + pf.y + bo3[1];
        ko.z = xa.z + pf.z + bo3[2];
        ko.w = xa.w + pf.w + bo3[3];

        float4 ka;
        if (stage == 0) {
            ka = ko;
        } else {
            ka = *(const float4*)(g_kacc + row * 4);
            float sc = (stage == 3) ? 1.0f : 2.0f;
            ka.x += sc * ko.x; ka.y += sc * ko.y;
            ka.z += sc * ko.z; ka.w += sc * ko.w;
        }

        if (stage < 3) {
            *(float4*)(g_kacc + row * 4) = ka;
            float cc = (stage == 2) ? dt : 0.5f * dt;
            float4 xn;
            xn.x = xs.x + cc * ko.x; xn.y = xs.y + cc * ko.y;
            xn.z = xs.z + cc * ko.z; xn.w = xs.w + cc * ko.w;
            *(float4*)(g_xarg + row * 4) = xn;
        } else {
            float cc = dt * (1.0f / 6.0f);
            float4 xn;
            xn.x = xs.x + cc * ka.x; xn.y = xs.y + cc * ka.y;
            xn.z = xs.z + cc * ka.z; xn.w = xs.w + cc * ka.w;
            *(float4*)(g_xst + row * 4) = xn;
            *(float4*)(g_xarg + row * 4) = xn;
            *(float4*)(outp + (row * NSTEP + step) * 4) = xn;
        }
    }
}

// ---------------- launch ------------------------------------------------------
extern "C" void kernel_launch(void* const* d_in, const int* in_sizes, int n_in,
                              void* d_out, int out_size)
{
    const float* inputs = (const float*)d_in[0];
    const float* edges  = (const float*)d_in[1];
    const float* W1  = (const float*)d_in[4];
    const float* b1  = (const float*)d_in[5];
    const float* W2  = (const float*)d_in[6];
    const float* b2  = (const float*)d_in[7];
    const float* Wo1 = (const float*)d_in[8];
    const float* bo1 = (const float*)d_in[9];
    const float* Wo2 = (const float*)d_in[10];
    const float* bo2 = (const float*)d_in[11];
    const float* Wo3 = (const float*)d_in[12];
    const float* bo3 = (const float*)d_in[13];
    float* outp = (float*)d_out;

    cudaFuncSetAttribute(edge_mma_kernel,
                         cudaFuncAttributeMaxDynamicSharedMemorySize, SMEM_TOT);

    init_kernel<<<(BB * NN * FI + 255) / 256, 256>>>(inputs);
    w2split_kernel<<<(2 * 256 * 256) / 256, 256>>>(W2);

    for (int step = 0; step < NSTEP; step++) {
        for (int stage = 0; stage < 4; stage++) {
            edge_mma_kernel<<<BB * 32, 256, SMEM_TOT>>>(edges, W1, b1, b2);
            node_kernel<<<BB * NN / 8, 256>>>(Wo1, bo1, Wo2, bo2, Wo3, bo3,
                                              outp, stage, step);
        }
    }
}

// round 6
// speedup vs baseline: 2.9475x; 1.5358x over previous
#include <cuda_runtime.h>
#include <cuda_fp16.h>
#include <cstdint>

// Problem constants
#define BB 32
#define NN 64
#define EE 4032
#define EPN 63
#define FI 4
#define NSTEP 10

// ---------------- scratch (device globals) ----------------------------------
__device__ float g_xst[BB * NN * FI];
__device__ float g_xarg[BB * NN * FI];
__device__ float g_kacc[BB * NN * FI];
__device__ float g_agg[BB * NN * 256];
// W2 split to fp16 hi/lo, pre-transposed: [k][ck][n][32 j]  (chunk-row layout)
__device__ __half g_w2h[2 * 256 * 256];
__device__ __half g_w2l[2 * 256 * 256];

// ---------------- smem layout (bytes) ----------------------------------------
#define SM_PRE   0        // 128 x 8 f32            (4096)
#define SM_EW    4096     // 128 x 2 f32            (1024)
#define SM_B1    5120     // 2 x 256 f32            (2048)
#define SM_B2    7168     // 2 x 256 f32            (2048)
#define SM_W1    9216     // 2 x 8 x 256 f32        (16384)
#define SM_PART  25600    // 2 x 4 x 256 f32        (8192)
#define SM_A     33792    // 2 bufs x 128 rows x 144B (Ah 64B | Al 64B | pad)
#define SM_B     70656    // 2 bufs x 2 reg x 256 rows x 80B (64B data | pad)
#define SMEM_TOT 152576

#define ABUF_BYTES 18432      // 128*144
#define BBUF_BYTES 40960      // 2*256*80
#define BREG_BYTES 20480      // 256*80

// ---------------- PTX helpers -------------------------------------------------
__device__ __forceinline__ uint32_t smem_u32(const void* p) {
    uint32_t a;
    asm("{ .reg .u64 t; cvta.to.shared.u64 t, %1; cvt.u32.u64 %0, t; }"
        : "=r"(a) : "l"(p));
    return a;
}
#define CP_ASYNC16(dst, src) \
    asm volatile("cp.async.cg.shared.global [%0], [%1], 16;" :: "r"(dst), "l"(src))
#define CP_COMMIT() asm volatile("cp.async.commit_group;" ::: "memory")
#define CP_WAIT1()  asm volatile("cp.async.wait_group 1;" ::: "memory")
#define CP_WAIT0()  asm volatile("cp.async.wait_group 0;" ::: "memory")

#define LDSM_X4(r0, r1, r2, r3, addr)                                        \
    asm volatile("ldmatrix.sync.aligned.m8n8.x4.shared.b16 {%0,%1,%2,%3}, [%4];" \
        : "=r"(r0), "=r"(r1), "=r"(r2), "=r"(r3) : "r"(addr))
#define LDSM_X2(r0, r1, addr)                                                \
    asm volatile("ldmatrix.sync.aligned.m8n8.x2.shared.b16 {%0,%1}, [%2];"   \
        : "=r"(r0), "=r"(r1) : "r"(addr))

#define MMA_F16(d, a, b0, b1)                                                \
    asm volatile("mma.sync.aligned.m16n8k16.row.col.f32.f16.f16.f32 "        \
        "{%0,%1,%2,%3}, {%4,%5,%6,%7}, {%8,%9}, {%0,%1,%2,%3};"              \
        : "+f"((d)[0]), "+f"((d)[1]), "+f"((d)[2]), "+f"((d)[3])             \
        : "r"((a)[0]), "r"((a)[1]), "r"((a)[2]), "r"((a)[3]),                \
          "r"(b0), "r"(b1))

// ---------------- init ----------------------------------------------------------
__global__ void init_kernel(const float* __restrict__ inputs)
{
    int i = blockIdx.x * blockDim.x + threadIdx.x;
    if (i < BB * NN * FI) {
        int f = i & 3;
        int row = i >> 2;
        float v = inputs[row * (11 * FI) + f];
        g_xst[i] = v;
        g_xarg[i] = v;
    }
}

// split W2 into fp16 hi + fp16 residual, transposed to [k][ck][n][j] chunk rows
__global__ void w2split_kernel(const float* __restrict__ W2)
{
    int i = blockIdx.x * blockDim.x + threadIdx.x;   // 131072
    int k = i >> 16;
    int hid = (i >> 8) & 255;
    int n = i & 255;
    float w = W2[i];
    __half ah = __float2half_rn(w);
    __half al = __float2half_rn(w - __half2float(ah));
    int ck = hid >> 5, j = hid & 31;
    size_t dst = ((size_t)(k * 8 + ck) * 256 + n) * 32 + j;
    g_w2h[dst] = ah;
    g_w2l[dst] = al;
}

// ---------------- edge kernel: fp16x2 split mma ---------------------------------
// CTA = (batch, 2 receivers). M=128 edge rows, N=256, K=256 hidden (x2 k-comp),
// 16 chunks of 32 hidden; each chunk = effective K 96 fp16 via 3-term split.
__global__ __launch_bounds__(256, 1) void edge_mma_kernel(
    const float* __restrict__ edges,
    const float* __restrict__ W1g, const float* __restrict__ b1g,
    const float* __restrict__ b2g)
{
    extern __shared__ float s[];
    uint32_t sb = smem_u32(s);
    const int t = threadIdx.x;
    const int wid = t >> 5, lane = t & 31;
    const int group = lane >> 2, tid4 = lane & 3;
    const int wm = wid & 3, wn = wid >> 2;          // 4 M-warps x 2 N-warps
    const int b = blockIdx.x >> 5;
    const int n0 = (blockIdx.x & 31) * 2;

    // ---- stage constants
    for (int i = t; i < 512; i += 256) {
        s[SM_B1 / 4 + i] = b1g[i];
        s[SM_B2 / 4 + i] = b2g[i];
    }
    for (int i = t; i < 4096; i += 256) s[SM_W1 / 4 + i] = W1g[i];
    if (t < 128) {
        int g = t >> 6, n = n0 + g, el = t & 63;
        float4 xs = make_float4(0.f, 0.f, 0.f, 0.f), xr = xs;
        float2 ew = make_float2(0.f, 0.f);
        if (el < EPN) {
            int send = (el < n) ? el : el + 1;
            xs = *(const float4*)(g_xarg + (b * NN + send) * 4);
            xr = *(const float4*)(g_xarg + (b * NN + n) * 4);
            ew = *(const float2*)(edges + ((long)(b * EE) + n * EPN + el) * 2);
        }
        float4* pr = (float4*)(s + SM_PRE / 4 + t * 8);
        pr[0] = xs; pr[1] = xr;
        s[SM_EW / 4 + t * 2 + 0] = ew.x;
        s[SM_EW / 4 + t * 2 + 1] = ew.y;
    }
    __syncthreads();

    // ---- staging helpers
    auto stage_w2 = [&](int c, int buf) {
        int k = c >> 3, ck = c & 7;
        const char* srch = (const char*)(g_w2h + (size_t)(k * 8 + ck) * 256 * 32);
        const char* srcl = (const char*)(g_w2l + (size_t)(k * 8 + ck) * 256 * 32);
        uint32_t db = sb + SM_B + (uint32_t)buf * BBUF_BYTES;
        #pragma unroll
        for (int i = 0; i < 4; i++) {
            int idx = t + i * 256;            // 0..1023
            int row = idx >> 2, seg = idx & 3;
            uint32_t doff = (uint32_t)(row * 80 + seg * 16);
            uint32_t soff = (uint32_t)(row * 64 + seg * 16);
            CP_ASYNC16(db + doff, srch + soff);
            CP_ASYNC16(db + BREG_BYTES + doff, srcl + soff);
        }
    };
    auto compute_h = [&](int c, int buf) {
        int k = c >> 3, ck = c & 7;
        int jp = t & 15, rg = t >> 4;
        int j0 = ck * 32 + 2 * jp;
        float w1a[8], w1b[8];
        #pragma unroll
        for (int f = 0; f < 8; f++) {
            w1a[f] = s[SM_W1 / 4 + (k * 8 + f) * 256 + j0];
            w1b[f] = s[SM_W1 / 4 + (k * 8 + f) * 256 + j0 + 1];
        }
        float b1a = s[SM_B1 / 4 + k * 256 + j0];
        float b1b = s[SM_B1 / 4 + k * 256 + j0 + 1];
        char* ab = (char*)s + SM_A + buf * ABUF_BYTES + jp * 4;
        #pragma unroll
        for (int rr = 0; rr < 8; rr++) {
            int r = rg * 8 + rr;
            const float4* pr = (const float4*)(s + SM_PRE / 4 + r * 8);
            float4 p0 = pr[0], p1 = pr[1];
            float h0 = b1a, h1 = b1b;
            h0 += p0.x * w1a[0]; h1 += p0.x * w1b[0];
            h0 += p0.y * w1a[1]; h1 += p0.y * w1b[1];
            h0 += p0.z * w1a[2]; h1 += p0.z * w1b[2];
            h0 += p0.w * w1a[3]; h1 += p0.w * w1b[3];
            h0 += p1.x * w1a[4]; h1 += p1.x * w1b[4];
            h0 += p1.y * w1a[5]; h1 += p1.y * w1b[5];
            h0 += p1.z * w1a[6]; h1 += p1.z * w1b[6];
            h0 += p1.w * w1a[7]; h1 += p1.w * w1b[7];
            h0 = fmaxf(h0, 0.f); h1 = fmaxf(h1, 0.f);
            __half ah0 = __float2half_rn(h0);
            __half ah1 = __float2half_rn(h1);
            __half al0 = __float2half_rn(h0 - __half2float(ah0));
            __half al1 = __float2half_rn(h1 - __half2float(ah1));
            __half2 hi = __halves2half2(ah0, ah1);
            __half2 lo = __halves2half2(al0, al1);
            *(uint32_t*)(ab + r * 144)      = *(uint32_t*)&hi;
            *(uint32_t*)(ab + r * 144 + 64) = *(uint32_t*)&lo;
        }
    };

    float acc[2][16][4];
    #pragma unroll
    for (int m = 0; m < 2; m++)
        #pragma unroll
        for (int nt = 0; nt < 16; nt++)
            #pragma unroll
            for (int q = 0; q < 4; q++) acc[m][nt][q] = 0.f;

    // per-thread invariant fragment addresses
    const uint32_t aRow = sb + SM_A + (uint32_t)(wm * 32 + (lane & 15)) * 144u
                        + ((lane & 16) ? 16u : 0u);
    const uint32_t bRow = sb + SM_B + (uint32_t)(wn * 128 + (lane & 7)) * 80u
                        + ((lane & 8) ? 16u : 0u);

    // prologue: chunk 0
    stage_w2(0, 0);
    CP_COMMIT();
    compute_h(0, 0);

    for (int c = 0; c < 16; c++) {
        int buf = c & 1;
        if (c < 15) {
            stage_w2(c + 1, 1 - buf);
            CP_COMMIT();
            compute_h(c + 1, 1 - buf);
            CP_WAIT1();
        } else {
            CP_WAIT0();
        }
        __syncthreads();

        // ---- fp16 split mma over chunk c: 6 eff k16-steps
        #pragma unroll
        for (int ks = 0; ks < 6; ks++) {
            uint32_t aoff = (uint32_t)buf * ABUF_BYTES
                          + ((ks < 4) ? 0u : 64u) + (uint32_t)(ks & 1) * 32u;
            uint32_t a[2][4];
            LDSM_X4(a[0][0], a[0][1], a[0][2], a[0][3], aRow + aoff);
            LDSM_X4(a[1][0], a[1][1], a[1][2], a[1][3], aRow + aoff + 16u * 144u);
            uint32_t boff = (uint32_t)buf * BBUF_BYTES
                          + ((ks == 2 || ks == 3) ? (uint32_t)BREG_BYTES : 0u)
                          + (uint32_t)(ks & 1) * 32u;
            uint32_t bbase = bRow + boff;
            #pragma unroll
            for (int nt = 0; nt < 16; nt++) {
                uint32_t b0, b1;
                LDSM_X2(b0, b1, bbase + (uint32_t)nt * 640u);
                MMA_F16(acc[0][nt], a[0], b0, b1);
                MMA_F16(acc[1][nt], a[1], b0, b1);
            }
        }

        // ---- epilogue for this k-component after its last chunk
        if ((c & 7) == 7) {
            int k = c >> 3;
            float colsum[32];
            #pragma unroll
            for (int i = 0; i < 32; i++) colsum[i] = 0.f;
            #pragma unroll
            for (int m = 0; m < 2; m++) {
                int rbase = wm * 32 + m * 16 + group;
                float ew0 = s[SM_EW / 4 + rbase * 2 + k];
                float ew1 = s[SM_EW / 4 + (rbase + 8) * 2 + k];
                #pragma unroll
                for (int nt = 0; nt < 16; nt++) {
                    int col0 = wn * 128 + nt * 8 + tid4 * 2;
                    float bz0 = s[SM_B2 / 4 + k * 256 + col0];
                    float bz1 = s[SM_B2 / 4 + k * 256 + col0 + 1];
                    colsum[nt * 2 + 0] += fmaxf(acc[m][nt][0] + bz0, 0.f) * ew0
                                        + fmaxf(acc[m][nt][2] + bz0, 0.f) * ew1;
                    colsum[nt * 2 + 1] += fmaxf(acc[m][nt][1] + bz1, 0.f) * ew0
                                        + fmaxf(acc[m][nt][3] + bz1, 0.f) * ew1;
                }
            }
            #pragma unroll
            for (int off = 4; off <= 16; off <<= 1)
                #pragma unroll
                for (int i = 0; i < 32; i++)
                    colsum[i] += __shfl_xor_sync(0xffffffffu, colsum[i], off);
            if (lane < 4) {
                float* dst = s + SM_PART / 4 + (k * 4 + wm) * 256 + wn * 128;
                #pragma unroll
                for (int nt = 0; nt < 16; nt++) {
                    dst[nt * 8 + lane * 2 + 0] = colsum[nt * 2 + 0];
                    dst[nt * 8 + lane * 2 + 1] = colsum[nt * 2 + 1];
                }
            }
            #pragma unroll
            for (int m = 0; m < 2; m++)
                #pragma unroll
                for (int nt = 0; nt < 16; nt++)
                    #pragma unroll
                    for (int q = 0; q < 4; q++) acc[m][nt][q] = 0.f;
        }
        __syncthreads();
    }

    // ---- final aggregation across k and M-warps
    {
        const float* p = s + SM_PART / 4;
        float a0 = p[0 * 256 + t] + p[1 * 256 + t] + p[4 * 256 + t] + p[5 * 256 + t];
        float a1 = p[2 * 256 + t] + p[3 * 256 + t] + p[6 * 256 + t] + p[7 * 256 + t];
        g_agg[(b * NN + n0) * 256 + t] = a0;
        g_agg[(b * NN + n0 + 1) * 256 + t] = a1;
    }
}

// ---------------- node kernel: output MLP + RK4 bookkeeping -------------------
__global__ __launch_bounds__(256) void node_kernel(
    const float* __restrict__ Wo1, const float* __restrict__ bo1,
    const float* __restrict__ Wo2, const float* __restrict__ bo2,
    const float* __restrict__ Wo3, const float* __restrict__ bo3,
    float* __restrict__ outp, int stage, int step)
{
    __shared__ float s_aug[8][264];
    __shared__ float s_h[8][264];
    __shared__ float s_h2[8][264];

    int r0 = blockIdx.x * 8;
    int t = threadIdx.x;

    for (int i = t; i < 8 * 264; i += 256) {
        int r = i / 264, c = i % 264;
        int row = r0 + r;
        float v = 0.f;
        if (c < 4) v = g_xarg[row * 4 + c];
        else if (c < 260) v = g_agg[row * 256 + (c - 4)];
        s_aug[r][c] = v;
    }
    __syncthreads();

    float acc[8];
    {
        float bv = bo1[t];
        #pragma unroll
        for (int r = 0; r < 8; r++) acc[r] = bv;
    }
    #pragma unroll 1
    for (int j = 0; j < 260; j += 4) {
        float w0 = __ldg(&Wo1[(j + 0) * 256 + t]);
        float w1 = __ldg(&Wo1[(j + 1) * 256 + t]);
        float w2 = __ldg(&Wo1[(j + 2) * 256 + t]);
        float w3 = __ldg(&Wo1[(j + 3) * 256 + t]);
        #pragma unroll
        for (int r = 0; r < 8; r++) {
            float4 a4 = *(const float4*)&s_aug[r][j];
            acc[r] += a4.x * w0 + a4.y * w1 + a4.z * w2 + a4.w * w3;
        }
    }
    #pragma unroll
    for (int r = 0; r < 8; r++) s_h[r][t] = fmaxf(acc[r], 0.f);
    __syncthreads();

    {
        float bv = bo2[t];
        #pragma unroll
        for (int r = 0; r < 8; r++) acc[r] = bv;
    }
    #pragma unroll 1
    for (int j = 0; j < 256; j += 4) {
        float w0 = __ldg(&Wo2[(j + 0) * 256 + t]);
        float w1 = __ldg(&Wo2[(j + 1) * 256 + t]);
        float w2 = __ldg(&Wo2[(j + 2) * 256 + t]);
        float w3 = __ldg(&Wo2[(j + 3) * 256 + t]);
        #pragma unroll
        for (int r = 0; r < 8; r++) {
            float4 a4 = *(const float4*)&s_h[r][j];
            acc[r] += a4.x * w0 + a4.y * w1 + a4.z * w2 + a4.w * w3;
        }
    }
    __syncthreads();
    #pragma unroll
    for (int r = 0; r < 8; r++) s_h2[r][t] = fmaxf(acc[r], 0.f);
    __syncthreads();

    int wr = t >> 5, lane = t & 31;
    float4 pf = make_float4(0.f, 0.f, 0.f, 0.f);
    for (int j = lane; j < 256; j += 32) {
        float v = s_h2[wr][j];
        float4 w3 = *(const float4*)(Wo3 + j * 4);
        pf.x += v * w3.x; pf.y += v * w3.y;
        pf.z += v * w3.z; pf.w += v * w3.w;
    }
    #pragma unroll
    for (int off = 16; off; off >>= 1) {
        pf.x += __shfl_xor_sync(0xffffffffu, pf.x, off);
        pf.y += __shfl_xor_sync(0xffffffffu, pf.y, off);
        pf.z += __shfl_xor_sync(0xffffffffu, pf.z, off);
        pf.w += __shfl_xor_sync(0xffffffffu, pf.w, off);
    }

    if (lane == 0) {
        int row = r0 + wr;
        float dt = (float)(step + 1) / 10.0f - (float)step / 10.0f;

        float4 xa = *(const float4*)(g_xarg + row * 4);
        float4 xs = *(const float4*)(g_xst + row * 4);

        float4 ko;
        ko.x = xa.x + pf.x + bo3[0];
        ko.y = xa.y + pf.y + bo3[1];
        ko.z = xa.z + pf.z + bo3[2];
        ko.w = xa.w + pf.w + bo3[3];

        float4 ka;
        if (stage == 0) {
            ka = ko;
        } else {
            ka = *(const float4*)(g_kacc + row * 4);
            float sc = (stage == 3) ? 1.0f : 2.0f;
            ka.x += sc * ko.x; ka.y += sc * ko.y;
            ka.z += sc * ko.z; ka.w += sc * ko.w;
        }

        if (stage < 3) {
            *(float4*)(g_kacc + row * 4) = ka;
            float cc = (stage == 2) ? dt : 0.5f * dt;
            float4 xn;
            xn.x = xs.x + cc * ko.x; xn.y = xs.y + cc * ko.y;
            xn.z = xs.z + cc * ko.z; xn.w = xs.w + cc * ko.w;
            *(float4*)(g_xarg + row * 4) = xn;
        } else {
            float cc = dt * (1.0f / 6.0f);
            float4 xn;
            xn.x = xs.x + cc * ka.x; xn.y = xs.y + cc * ka.y;
            xn.z = xs.z + cc * ka.z; xn.w = xs.w + cc * ka.w;
            *(float4*)(g_xst + row * 4) = xn;
            *(float4*)(g_xarg + row * 4) = xn;
            *(float4*)(outp + (row * NSTEP + step) * 4) = xn;
        }
    }
}

// ---------------- launch ------------------------------------------------------
extern "C" void kernel_launch(void* const* d_in, const int* in_sizes, int n_in,
                              void* d_out, int out_size)
{
    const float* inputs = (const float*)d_in[0];
    const float* edges  = (const float*)d_in[1];
    const float* W1  = (const float*)d_in[4];
    const float* b1  = (const float*)d_in[5];
    const float* W2  = (const float*)d_in[6];
    const float* b2  = (const float*)d_in[7];
    const float* Wo1 = (const float*)d_in[8];
    const float* bo1 = (const float*)d_in[9];
    const float* Wo2 = (const float*)d_in[10];
    const float* bo2 = (const float*)d_in[11];
    const float* Wo3 = (const float*)d_in[12];
    const float* bo3 = (const float*)d_in[13];
    float* outp = (float*)d_out;

    cudaFuncSetAttribute(edge_mma_kernel,
                         cudaFuncAttributeMaxDynamicSharedMemorySize, SMEM_TOT);

    init_kernel<<<(BB * NN * FI + 255) / 256, 256>>>(inputs);
    w2split_kernel<<<(2 * 256 * 256) / 256, 256>>>(W2);

    for (int step = 0; step < NSTEP; step++) {
        for (int stage = 0; stage < 4; stage++) {
            edge_mma_kernel<<<BB * 32, 256, SMEM_TOT>>>(edges, W1, b1, b2);
            node_kernel<<<BB * NN / 8, 256>>>(Wo1, bo1, Wo2, bo2, Wo3, bo3,
                                              outp, stage, step);
        }
    }
}

// round 7
// speedup vs baseline: 2.9515x; 1.0013x over previous
#include <cuda_runtime.h>
#include <cuda_fp16.h>
#include <cstdint>

// Problem constants
#define BB 32
#define NN 64
#define EE 4032
#define EPN 63
#define FI 4
#define NSTEP 10

// ---------------- scratch (device globals) ----------------------------------
__device__ float g_xst[BB * NN * FI];
__device__ float g_xarg[BB * NN * FI];
__device__ float g_kacc[BB * NN * FI];
__device__ float g_agg[BB * NN * 256];
// W2 split to fp16 hi/lo, pre-transposed: [k][ck][n][32 j]  (chunk-row layout)
__device__ __half g_w2h[2 * 256 * 256];
__device__ __half g_w2l[2 * 256 * 256];

// ---------------- smem layout (bytes) ----------------------------------------
#define SM_PRE   0        // 128 x 8 f32            (4096)
#define SM_EW    4096     // 128 x 2 f32            (1024)
#define SM_B1    5120     // 2 x 256 f32            (2048)
#define SM_B2    7168     // 2 x 256 f32            (2048)
#define SM_W1    9216     // 2 x 8 x 256 f32        (16384)
#define SM_PART  25600    // 2 x 4 x 256 f32        (8192)
#define SM_A     33792    // 2 bufs x 128 rows x 144B (Ah 64B | Al 64B | pad)
#define SM_B     70656    // 2 bufs x 2 reg x 256 rows x 80B (64B data | pad)
#define SMEM_TOT 152576

#define ABUF_BYTES 18432      // 128*144
#define BBUF_BYTES 40960      // 2*256*80
#define BREG_BYTES 20480      // 256*80

// ---------------- PTX helpers -------------------------------------------------
__device__ __forceinline__ uint32_t smem_u32(const void* p) {
    uint32_t a;
    asm("{ .reg .u64 t; cvta.to.shared.u64 t, %1; cvt.u32.u64 %0, t; }"
        : "=r"(a) : "l"(p));
    return a;
}
#define CP_ASYNC16(dst, src) \
    asm volatile("cp.async.cg.shared.global [%0], [%1], 16;" :: "r"(dst), "l"(src))
#define CP_COMMIT() asm volatile("cp.async.commit_group;" ::: "memory")
#define CP_WAIT1()  asm volatile("cp.async.wait_group 1;" ::: "memory")
#define CP_WAIT0()  asm volatile("cp.async.wait_group 0;" ::: "memory")

#define LDSM_X4(r0, r1, r2, r3, addr)                                        \
    asm volatile("ldmatrix.sync.aligned.m8n8.x4.shared.b16 {%0,%1,%2,%3}, [%4];" \
        : "=r"(r0), "=r"(r1), "=r"(r2), "=r"(r3) : "r"(addr))

#define MMA_F16(d, a, b0, b1)                                                \
    asm volatile("mma.sync.aligned.m16n8k16.row.col.f32.f16.f16.f32 "        \
        "{%0,%1,%2,%3}, {%4,%5,%6,%7}, {%8,%9}, {%0,%1,%2,%3};"              \
        : "+f"((d)[0]), "+f"((d)[1]), "+f"((d)[2]), "+f"((d)[3])             \
        : "r"((a)[0]), "r"((a)[1]), "r"((a)[2]), "r"((a)[3]),                \
          "r"(b0), "r"(b1))

// ---------------- init ----------------------------------------------------------
__global__ void init_kernel(const float* __restrict__ inputs)
{
    int i = blockIdx.x * blockDim.x + threadIdx.x;
    if (i < BB * NN * FI) {
        int f = i & 3;
        int row = i >> 2;
        float v = inputs[row * (11 * FI) + f];
        g_xst[i] = v;
        g_xarg[i] = v;
    }
}

// split W2 into fp16 hi + fp16 residual, transposed to [k][ck][n][j] chunk rows
__global__ void w2split_kernel(const float* __restrict__ W2)
{
    int i = blockIdx.x * blockDim.x + threadIdx.x;   // 131072
    int k = i >> 16;
    int hid = (i >> 8) & 255;
    int n = i & 255;
    float w = W2[i];
    __half ah = __float2half_rn(w);
    __half al = __float2half_rn(w - __half2float(ah));
    int ck = hid >> 5, j = hid & 31;
    size_t dst = ((size_t)(k * 8 + ck) * 256 + n) * 32 + j;
    g_w2h[dst] = ah;
    g_w2l[dst] = al;
}

// ---------------- edge kernel: fp16x2 split mma ---------------------------------
// CTA = (batch, 2 receivers). M=128 edge rows, N=256, K=256 hidden (x2 k-comp),
// 16 chunks of 32 hidden; each chunk = effective K 96 fp16 via 3-term split.
__global__ __launch_bounds__(256, 1) void edge_mma_kernel(
    const float* __restrict__ edges,
    const float* __restrict__ W1g, const float* __restrict__ b1g,
    const float* __restrict__ b2g)
{
    extern __shared__ float s[];
    uint32_t sb = smem_u32(s);
    const int t = threadIdx.x;
    const int wid = t >> 5, lane = t & 31;
    const int group = lane >> 2, tid4 = lane & 3;
    const int wm = wid & 3, wn = wid >> 2;          // 4 M-warps x 2 N-warps
    const int b = blockIdx.x >> 5;
    const int n0 = (blockIdx.x & 31) * 2;

    // ---- stage constants
    for (int i = t; i < 512; i += 256) {
        s[SM_B1 / 4 + i] = b1g[i];
        s[SM_B2 / 4 + i] = b2g[i];
    }
    for (int i = t; i < 4096; i += 256) s[SM_W1 / 4 + i] = W1g[i];
    if (t < 128) {
        int g = t >> 6, n = n0 + g, el = t & 63;
        float4 xs = make_float4(0.f, 0.f, 0.f, 0.f), xr = xs;
        float2 ew = make_float2(0.f, 0.f);
        if (el < EPN) {
            int send = (el < n) ? el : el + 1;
            xs = *(const float4*)(g_xarg + (b * NN + send) * 4);
            xr = *(const float4*)(g_xarg + (b * NN + n) * 4);
            ew = *(const float2*)(edges + ((long)(b * EE) + n * EPN + el) * 2);
        }
        float4* pr = (float4*)(s + SM_PRE / 4 + t * 8);
        pr[0] = xs; pr[1] = xr;
        s[SM_EW / 4 + t * 2 + 0] = ew.x;
        s[SM_EW / 4 + t * 2 + 1] = ew.y;
    }
    __syncthreads();

    // ---- staging helpers
    auto stage_w2 = [&](int c, int buf) {
        int k = c >> 3, ck = c & 7;
        const char* srch = (const char*)(g_w2h + (size_t)(k * 8 + ck) * 256 * 32);
        const char* srcl = (const char*)(g_w2l + (size_t)(k * 8 + ck) * 256 * 32);
        uint32_t db = sb + SM_B + (uint32_t)buf * BBUF_BYTES;
        #pragma unroll
        for (int i = 0; i < 4; i++) {
            int idx = t + i * 256;            // 0..1023
            int row = idx >> 2, seg = idx & 3;
            uint32_t doff = (uint32_t)(row * 80 + seg * 16);
            uint32_t soff = (uint32_t)(row * 64 + seg * 16);
            CP_ASYNC16(db + doff, srch + soff);
            CP_ASYNC16(db + BREG_BYTES + doff, srcl + soff);
        }
    };
    auto compute_h = [&](int c, int buf) {
        int k = c >> 3, ck = c & 7;
        int jp = t & 15, rg = t >> 4;
        int j0 = ck * 32 + 2 * jp;
        float w1a[8], w1b[8];
        #pragma unroll
        for (int f = 0; f < 8; f++) {
            w1a[f] = s[SM_W1 / 4 + (k * 8 + f) * 256 + j0];
            w1b[f] = s[SM_W1 / 4 + (k * 8 + f) * 256 + j0 + 1];
        }
        float b1a = s[SM_B1 / 4 + k * 256 + j0];
        float b1b = s[SM_B1 / 4 + k * 256 + j0 + 1];
        char* ab = (char*)s + SM_A + buf * ABUF_BYTES + jp * 4;
        #pragma unroll
        for (int rr = 0; rr < 8; rr++) {
            int r = rg * 8 + rr;
            const float4* pr = (const float4*)(s + SM_PRE / 4 + r * 8);
            float4 p0 = pr[0], p1 = pr[1];
            float h0 = b1a, h1 = b1b;
            h0 += p0.x * w1a[0]; h1 += p0.x * w1b[0];
            h0 += p0.y * w1a[1]; h1 += p0.y * w1b[1];
            h0 += p0.z * w1a[2]; h1 += p0.z * w1b[2];
            h0 += p0.w * w1a[3]; h1 += p0.w * w1b[3];
            h0 += p1.x * w1a[4]; h1 += p1.x * w1b[4];
            h0 += p1.y * w1a[5]; h1 += p1.y * w1b[5];
            h0 += p1.z * w1a[6]; h1 += p1.z * w1b[6];
            h0 += p1.w * w1a[7]; h1 += p1.w * w1b[7];
            h0 = fmaxf(h0, 0.f); h1 = fmaxf(h1, 0.f);
            __half ah0 = __float2half_rn(h0);
            __half ah1 = __float2half_rn(h1);
            __half al0 = __float2half_rn(h0 - __half2float(ah0));
            __half al1 = __float2half_rn(h1 - __half2float(ah1));
            __half2 hi = __halves2half2(ah0, ah1);
            __half2 lo = __halves2half2(al0, al1);
            *(uint32_t*)(ab + r * 144)      = *(uint32_t*)&hi;
            *(uint32_t*)(ab + r * 144 + 64) = *(uint32_t*)&lo;
        }
    };

    float acc[2][16][4];
    #pragma unroll
    for (int m = 0; m < 2; m++)
        #pragma unroll
        for (int nt = 0; nt < 16; nt++)
            #pragma unroll
            for (int q = 0; q < 4; q++) acc[m][nt][q] = 0.f;

    // per-thread invariant fragment addresses
    const uint32_t aRow = sb + SM_A + (uint32_t)(wm * 32 + (lane & 15)) * 144u
                        + ((lane & 16) ? 16u : 0u);
    // B x4: lanes 0-7 rows nt*8.., 8-15 same +16B, 16-23 rows (nt+1)*8.., 24-31 +16B
    const uint32_t bRow = sb + SM_B
                        + (uint32_t)(wn * 128 + (lane & 7) + ((lane >> 4) & 1) * 8) * 80u
                        + (uint32_t)((lane >> 3) & 1) * 16u;

    // prologue: chunk 0
    stage_w2(0, 0);
    CP_COMMIT();
    compute_h(0, 0);

    for (int c = 0; c < 16; c++) {
        int buf = c & 1;
        if (c < 15) {
            stage_w2(c + 1, 1 - buf);
            CP_COMMIT();
            compute_h(c + 1, 1 - buf);
            CP_WAIT1();
        } else {
            CP_WAIT0();
        }
        __syncthreads();

        // ---- fp16 split mma over chunk c: 6 eff k16-steps
        #pragma unroll
        for (int ks = 0; ks < 6; ks++) {
            uint32_t aoff = (uint32_t)buf * ABUF_BYTES
                          + ((ks < 4) ? 0u : 64u) + (uint32_t)(ks & 1) * 32u;
            uint32_t a[2][4];
            LDSM_X4(a[0][0], a[0][1], a[0][2], a[0][3], aRow + aoff);
            LDSM_X4(a[1][0], a[1][1], a[1][2], a[1][3], aRow + aoff + 16u * 144u);
            uint32_t boff = (uint32_t)buf * BBUF_BYTES
                          + ((ks == 2 || ks == 3) ? (uint32_t)BREG_BYTES : 0u)
                          + (uint32_t)(ks & 1) * 32u;
            uint32_t bbase = bRow + boff;
            #pragma unroll
            for (int ntp = 0; ntp < 8; ntp++) {
                uint32_t b0, b1, b2, b3;
                LDSM_X4(b0, b1, b2, b3, bbase + (uint32_t)ntp * 1280u);
                MMA_F16(acc[0][2 * ntp],     a[0], b0, b1);
                MMA_F16(acc[1][2 * ntp],     a[1], b0, b1);
                MMA_F16(acc[0][2 * ntp + 1], a[0], b2, b3);
                MMA_F16(acc[1][2 * ntp + 1], a[1], b2, b3);
            }
        }

        // ---- epilogue for this k-component after its last chunk
        if ((c & 7) == 7) {
            int k = c >> 3;
            float colsum[32];
            #pragma unroll
            for (int i = 0; i < 32; i++) colsum[i] = 0.f;
            #pragma unroll
            for (int m = 0; m < 2; m++) {
                int rbase = wm * 32 + m * 16 + group;
                float ew0 = s[SM_EW / 4 + rbase * 2 + k];
                float ew1 = s[SM_EW / 4 + (rbase + 8) * 2 + k];
                #pragma unroll
                for (int nt = 0; nt < 16; nt++) {
                    int col0 = wn * 128 + nt * 8 + tid4 * 2;
                    float bz0 = s[SM_B2 / 4 + k * 256 + col0];
                    float bz1 = s[SM_B2 / 4 + k * 256 + col0 + 1];
                    colsum[nt * 2 + 0] += fmaxf(acc[m][nt][0] + bz0, 0.f) * ew0
                                        + fmaxf(acc[m][nt][2] + bz0, 0.f) * ew1;
                    colsum[nt * 2 + 1] += fmaxf(acc[m][nt][1] + bz1, 0.f) * ew0
                                        + fmaxf(acc[m][nt][3] + bz1, 0.f) * ew1;
                }
            }
            #pragma unroll
            for (int off = 4; off <= 16; off <<= 1)
                #pragma unroll
                for (int i = 0; i < 32; i++)
                    colsum[i] += __shfl_xor_sync(0xffffffffu, colsum[i], off);
            if (lane < 4) {
                float* dst = s + SM_PART / 4 + (k * 4 + wm) * 256 + wn * 128;
                #pragma unroll
                for (int nt = 0; nt < 16; nt++) {
                    dst[nt * 8 + lane * 2 + 0] = colsum[nt * 2 + 0];
                    dst[nt * 8 + lane * 2 + 1] = colsum[nt * 2 + 1];
                }
            }
            #pragma unroll
            for (int m = 0; m < 2; m++)
                #pragma unroll
                for (int nt = 0; nt < 16; nt++)
                    #pragma unroll
                    for (int q = 0; q < 4; q++) acc[m][nt][q] = 0.f;
        }
        __syncthreads();
    }

    // ---- final aggregation across k and M-warps
    {
        const float* p = s + SM_PART / 4;
        float a0 = p[0 * 256 + t] + p[1 * 256 + t] + p[4 * 256 + t] + p[5 * 256 + t];
        float a1 = p[2 * 256 + t] + p[3 * 256 + t] + p[6 * 256 + t] + p[7 * 256 + t];
        g_agg[(b * NN + n0) * 256 + t] = a0;
        g_agg[(b * NN + n0 + 1) * 256 + t] = a1;
    }
}

// ---------------- node kernel: output MLP + RK4 bookkeeping -------------------
// 16 rows per block, 128 blocks (one full wave). Thread t owns column t.
#define NROWS 16
__global__ __launch_bounds__(256) void node_kernel(
    const float* __restrict__ Wo1, const float* __restrict__ bo1,
    const float* __restrict__ Wo2, const float* __restrict__ bo2,
    const float* __restrict__ Wo3, const float* __restrict__ bo3,
    float* __restrict__ outp, int stage, int step)
{
    __shared__ float s_a[NROWS][264];   // aug, later reused as h2
    __shared__ float s_h[NROWS][264];

    int r0 = blockIdx.x * NROWS;
    int t = threadIdx.x;

    for (int i = t; i < NROWS * 264; i += 256) {
        int r = i / 264, c = i % 264;
        int row = r0 + r;
        float v = 0.f;
        if (c < 4) v = g_xarg[row * 4 + c];
        else if (c < 260) v = g_agg[row * 256 + (c - 4)];
        s_a[r][c] = v;
    }
    __syncthreads();

    float acc[NROWS];
    {
        float bv = bo1[t];
        #pragma unroll
        for (int r = 0; r < NROWS; r++) acc[r] = bv;
    }
    #pragma unroll 1
    for (int j = 0; j < 260; j += 4) {
        float w0 = __ldg(&Wo1[(j + 0) * 256 + t]);
        float w1 = __ldg(&Wo1[(j + 1) * 256 + t]);
        float w2 = __ldg(&Wo1[(j + 2) * 256 + t]);
        float w3 = __ldg(&Wo1[(j + 3) * 256 + t]);
        #pragma unroll
        for (int r = 0; r < NROWS; r++) {
            float4 a4 = *(const float4*)&s_a[r][j];
            acc[r] += a4.x * w0 + a4.y * w1 + a4.z * w2 + a4.w * w3;
        }
    }
    #pragma unroll
    for (int r = 0; r < NROWS; r++) s_h[r][t] = fmaxf(acc[r], 0.f);
    __syncthreads();

    {
        float bv = bo2[t];
        #pragma unroll
        for (int r = 0; r < NROWS; r++) acc[r] = bv;
    }
    #pragma unroll 1
    for (int j = 0; j < 256; j += 4) {
        float w0 = __ldg(&Wo2[(j + 0) * 256 + t]);
        float w1 = __ldg(&Wo2[(j + 1) * 256 + t]);
        float w2 = __ldg(&Wo2[(j + 2) * 256 + t]);
        float w3 = __ldg(&Wo2[(j + 3) * 256 + t]);
        #pragma unroll
        for (int r = 0; r < NROWS; r++) {
            float4 a4 = *(const float4*)&s_h[r][j];
            acc[r] += a4.x * w0 + a4.y * w1 + a4.z * w2 + a4.w * w3;
        }
    }
    __syncthreads();
    #pragma unroll
    for (int r = 0; r < NROWS; r++) s_a[r][t] = fmaxf(acc[r], 0.f);   // h2 in s_a
    __syncthreads();

    // final 256->4 projection: warp w handles rows 2w, 2w+1
    int wr = t >> 5, lane = t & 31;
    #pragma unroll
    for (int rr = 0; rr < 2; rr++) {
        int rl = wr * 2 + rr;
        float4 pf = make_float4(0.f, 0.f, 0.f, 0.f);
        for (int j = lane; j < 256; j += 32) {
            float v = s_a[rl][j];
            float4 w3 = *(const float4*)(Wo3 + j * 4);
            pf.x += v * w3.x; pf.y += v * w3.y;
            pf.z += v * w3.z; pf.w += v * w3.w;
        }
        #pragma unroll
        for (int off = 16; off; off >>= 1) {
            pf.x += __shfl_xor_sync(0xffffffffu, pf.x, off);
            pf.y += __shfl_xor_sync(0xffffffffu, pf.y, off);
            pf.z += __shfl_xor_sync(0xffffffffu, pf.z, off);
            pf.w += __shfl_xor_sync(0xffffffffu, pf.w, off);
        }

        if (lane == 0) {
            int row = r0 + rl;
            float dt = (float)(step + 1) / 10.0f - (float)step / 10.0f;

            float4 xa = *(const float4*)(g_xarg + row * 4);
            float4 xs = *(const float4*)(g_xst + row * 4);

            float4 ko;
            ko.x = xa.x + pf.x + bo3[0];
            ko.y = xa.y + pf.y + bo3[1];
            ko.z = xa.z + pf.z + bo3[2];
            ko.w = xa.w + pf.w + bo3[3];

            float4 ka;
            if (stage == 0) {
                ka = ko;
            } else {
                ka = *(const float4*)(g_kacc + row * 4);
                float sc = (stage == 3) ? 1.0f : 2.0f;
                ka.x += sc * ko.x; ka.y += sc * ko.y;
                ka.z += sc * ko.z; ka.w += sc * ko.w;
            }

            if (stage < 3) {
                *(float4*)(g_kacc + row * 4) = ka;
                float cc = (stage == 2) ? dt : 0.5f * dt;
                float4 xn;
                xn.x = xs.x + cc * ko.x; xn.y = xs.y + cc * ko.y;
                xn.z = xs.z + cc * ko.z; xn.w = xs.w + cc * ko.w;
                *(float4*)(g_xarg + row * 4) = xn;
            } else {
                float cc = dt * (1.0f / 6.0f);
                float4 xn;
                xn.x = xs.x + cc * ka.x; xn.y = xs.y + cc * ka.y;
                xn.z = xs.z + cc * ka.z; xn.w = xs.w + cc * ka.w;
                *(float4*)(g_xst + row * 4) = xn;
                *(float4*)(g_xarg + row * 4) = xn;
                *(float4*)(outp + (row * NSTEP + step) * 4) = xn;
            }
        }
    }
}

// ---------------- launch ------------------------------------------------------
extern "C" void kernel_launch(void* const* d_in, const int* in_sizes, int n_in,
                              void* d_out, int out_size)
{
    const float* inputs = (const float*)d_in[0];
    const float* edges  = (const float*)d_in[1];
    const float* W1  = (const float*)d_in[4];
    const float* b1  = (const float*)d_in[5];
    const float* W2  = (const float*)d_in[6];
    const float* b2  = (const float*)d_in[7];
    const float* Wo1 = (const float*)d_in[8];
    const float* bo1 = (const float*)d_in[9];
    const float* Wo2 = (const float*)d_in[10];
    const float* bo2 = (const float*)d_in[11];
    const float* Wo3 = (const float*)d_in[12];
    const float* bo3 = (const float*)d_in[13];
    float* outp = (float*)d_out;

    cudaFuncSetAttribute(edge_mma_kernel,
                         cudaFuncAttributeMaxDynamicSharedMemorySize, SMEM_TOT);

    init_kernel<<<(BB * NN * FI + 255) / 256, 256>>>(inputs);
    w2split_kernel<<<(2 * 256 * 256) / 256, 256>>>(W2);

    for (int step = 0; step < NSTEP; step++) {
        for (int stage = 0; stage < 4; stage++) {
            edge_mma_kernel<<<BB * 32, 256, SMEM_TOT>>>(edges, W1, b1, b2);
            node_kernel<<<BB * NN / NROWS, 256>>>(Wo1, bo1, Wo2, bo2, Wo3, bo3,
                                                  outp, stage, step);
        }
    }
}

// round 8
// speedup vs baseline: 3.1598x; 1.0706x over previous
#include <cuda_runtime.h>
#include <cuda_fp16.h>
#include <cstdint>

// Problem constants
#define BB 32
#define NN 64
#define EE 4032
#define EPN 63
#define FI 4
#define NSTEP 10

// ---------------- scratch (device globals) ----------------------------------
__device__ float g_xst[BB * NN * FI];
__device__ float g_xarg[BB * NN * FI];
__device__ float g_kacc[BB * NN * FI];
__device__ float g_agg[BB * NN * 256];
// W2 split to fp16 hi/lo, pre-transposed: [k][ck][n][32 j]  (chunk-row layout)
__device__ __half g_w2h[2 * 256 * 256];
__device__ __half g_w2l[2 * 256 * 256];

// ---------------- smem layout (bytes) ----------------------------------------
#define SM_PRE   0        // 128 x 8 f32            (4096)
#define SM_EW    4096     // 128 x 2 f32            (1024)
#define SM_B1    5120     // 2 x 256 f32            (2048)
#define SM_B2    7168     // 2 x 256 f32            (2048)
#define SM_W1    9216     // 2 x 8 x 256 f32        (16384)
#define SM_PART  25600    // 2 x 4 x 128 f32        (4096)
#define SM_A     29696    // 2 bufs x 128 rows x 144B (Ah 64B | Al 64B | pad)
#define SM_B     66560    // 2 bufs x 2 reg x 128 rows x 80B (64B data | pad)
#define SMEM_TOT 107520

#define ABUF_BYTES 18432      // 128*144
#define BBUF_BYTES 20480      // 2*128*80
#define BREG_BYTES 10240      // 128*80

// ---------------- PTX helpers -------------------------------------------------
__device__ __forceinline__ uint32_t smem_u32(const void* p) {
    uint32_t a;
    asm("{ .reg .u64 t; cvta.to.shared.u64 t, %1; cvt.u32.u64 %0, t; }"
        : "=r"(a) : "l"(p));
    return a;
}
#define CP_ASYNC16(dst, src) \
    asm volatile("cp.async.cg.shared.global [%0], [%1], 16;" :: "r"(dst), "l"(src))
#define CP_COMMIT() asm volatile("cp.async.commit_group;" ::: "memory")
#define CP_WAIT1()  asm volatile("cp.async.wait_group 1;" ::: "memory")
#define CP_WAIT0()  asm volatile("cp.async.wait_group 0;" ::: "memory")

#define LDSM_X4(r0, r1, r2, r3, addr)                                        \
    asm volatile("ldmatrix.sync.aligned.m8n8.x4.shared.b16 {%0,%1,%2,%3}, [%4];" \
        : "=r"(r0), "=r"(r1), "=r"(r2), "=r"(r3) : "r"(addr))

#define MMA_F16(d, a, b0, b1)                                                \
    asm volatile("mma.sync.aligned.m16n8k16.row.col.f32.f16.f16.f32 "        \
        "{%0,%1,%2,%3}, {%4,%5,%6,%7}, {%8,%9}, {%0,%1,%2,%3};"              \
        : "+f"((d)[0]), "+f"((d)[1]), "+f"((d)[2]), "+f"((d)[3])             \
        : "r"((a)[0]), "r"((a)[1]), "r"((a)[2]), "r"((a)[3]),                \
          "r"(b0), "r"(b1))

// ---------------- init ----------------------------------------------------------
__global__ void init_kernel(const float* __restrict__ inputs)
{
    int i = blockIdx.x * blockDim.x + threadIdx.x;
    if (i < BB * NN * FI) {
        int f = i & 3;
        int row = i >> 2;
        float v = inputs[row * (11 * FI) + f];
        g_xst[i] = v;
        g_xarg[i] = v;
    }
}

// split W2 into fp16 hi + fp16 residual, transposed to [k][ck][n][j] chunk rows
__global__ void w2split_kernel(const float* __restrict__ W2)
{
    int i = blockIdx.x * blockDim.x + threadIdx.x;   // 131072
    int k = i >> 16;
    int hid = (i >> 8) & 255;
    int n = i & 255;
    float w = W2[i];
    __half ah = __float2half_rn(w);
    __half al = __float2half_rn(w - __half2float(ah));
    int ck = hid >> 5, j = hid & 31;
    size_t dst = ((size_t)(k * 8 + ck) * 256 + n) * 32 + j;
    g_w2h[dst] = ah;
    g_w2l[dst] = al;
}

// ---------------- edge kernel: fp16x2 split mma ---------------------------------
// CTA = (batch, 2 receivers, N-half). M=128 edge rows, N=128 of 256 outputs,
// K=256 hidden (x2 k-comp), 16 chunks of 32; chunk = eff K96 fp16 3-term split.
// 2 CTAs per SM (smem 105 KB, <=128 regs) for latency hiding.
__global__ __launch_bounds__(256, 2) void edge_mma_kernel(
    const float* __restrict__ edges,
    const float* __restrict__ W1g, const float* __restrict__ b1g,
    const float* __restrict__ b2g)
{
    extern __shared__ float s[];
    uint32_t sb = smem_u32(s);
    const int t = threadIdx.x;
    const int wid = t >> 5, lane = t & 31;
    const int group = lane >> 2, tid4 = lane & 3;
    const int wm = wid & 3, wn = wid >> 2;          // 4 M-warps x 2 N-warps
    const int b = blockIdx.x >> 6;
    const int sub = blockIdx.x & 63;
    const int n0 = (sub >> 1) * 2;                  // receiver tile
    const int nh = sub & 1;                         // N half: cols nh*128..+127

    // ---- stage constants
    for (int i = t; i < 512; i += 256) {
        s[SM_B1 / 4 + i] = b1g[i];
        s[SM_B2 / 4 + i] = b2g[i];
    }
    for (int i = t; i < 4096; i += 256) s[SM_W1 / 4 + i] = W1g[i];
    if (t < 128) {
        int g = t >> 6, n = n0 + g, el = t & 63;
        float4 xs = make_float4(0.f, 0.f, 0.f, 0.f), xr = xs;
        float2 ew = make_float2(0.f, 0.f);
        if (el < EPN) {
            int send = (el < n) ? el : el + 1;
            xs = *(const float4*)(g_xarg + (b * NN + send) * 4);
            xr = *(const float4*)(g_xarg + (b * NN + n) * 4);
            ew = *(const float2*)(edges + ((long)(b * EE) + n * EPN + el) * 2);
        }
        float4* pr = (float4*)(s + SM_PRE / 4 + t * 8);
        pr[0] = xs; pr[1] = xr;
        s[SM_EW / 4 + t * 2 + 0] = ew.x;
        s[SM_EW / 4 + t * 2 + 1] = ew.y;
    }
    __syncthreads();

    // ---- staging helpers
    auto stage_w2 = [&](int c, int buf) {
        int k = c >> 3, ck = c & 7;
        size_t off = ((size_t)(k * 8 + ck) * 256 + nh * 128) * 32;
        const char* srch = (const char*)(g_w2h + off);
        const char* srcl = (const char*)(g_w2l + off);
        uint32_t db = sb + SM_B + (uint32_t)buf * BBUF_BYTES;
        #pragma unroll
        for (int i = 0; i < 2; i++) {
            int idx = t + i * 256;            // 0..511
            int row = idx >> 2, seg = idx & 3;
            uint32_t doff = (uint32_t)(row * 80 + seg * 16);
            uint32_t soff = (uint32_t)(row * 64 + seg * 16);
            CP_ASYNC16(db + doff, srch + soff);
            CP_ASYNC16(db + BREG_BYTES + doff, srcl + soff);
        }
    };
    auto compute_h = [&](int c, int buf) {
        int k = c >> 3, ck = c & 7;
        int jp = t & 15, rg = t >> 4;
        int j0 = ck * 32 + 2 * jp;
        float w1a[8], w1b[8];
        #pragma unroll
        for (int f = 0; f < 8; f++) {
            w1a[f] = s[SM_W1 / 4 + (k * 8 + f) * 256 + j0];
            w1b[f] = s[SM_W1 / 4 + (k * 8 + f) * 256 + j0 + 1];
        }
        float b1a = s[SM_B1 / 4 + k * 256 + j0];
        float b1b = s[SM_B1 / 4 + k * 256 + j0 + 1];
        char* ab = (char*)s + SM_A + buf * ABUF_BYTES + jp * 4;
        #pragma unroll
        for (int rr = 0; rr < 8; rr++) {
            int r = rg * 8 + rr;
            const float4* pr = (const float4*)(s + SM_PRE / 4 + r * 8);
            float4 p0 = pr[0], p1 = pr[1];
            float h0 = b1a, h1 = b1b;
            h0 += p0.x * w1a[0]; h1 += p0.x * w1b[0];
            h0 += p0.y * w1a[1]; h1 += p0.y * w1b[1];
            h0 += p0.z * w1a[2]; h1 += p0.z * w1b[2];
            h0 += p0.w * w1a[3]; h1 += p0.w * w1b[3];
            h0 += p1.x * w1a[4]; h1 += p1.x * w1b[4];
            h0 += p1.y * w1a[5]; h1 += p1.y * w1b[5];
            h0 += p1.z * w1a[6]; h1 += p1.z * w1b[6];
            h0 += p1.w * w1a[7]; h1 += p1.w * w1b[7];
            h0 = fmaxf(h0, 0.f); h1 = fmaxf(h1, 0.f);
            __half ah0 = __float2half_rn(h0);
            __half ah1 = __float2half_rn(h1);
            __half al0 = __float2half_rn(h0 - __half2float(ah0));
            __half al1 = __float2half_rn(h1 - __half2float(ah1));
            __half2 hi = __halves2half2(ah0, ah1);
            __half2 lo = __halves2half2(al0, al1);
            *(uint32_t*)(ab + r * 144)      = *(uint32_t*)&hi;
            *(uint32_t*)(ab + r * 144 + 64) = *(uint32_t*)&lo;
        }
    };

    float acc[2][8][4];
    #pragma unroll
    for (int m = 0; m < 2; m++)
        #pragma unroll
        for (int nt = 0; nt < 8; nt++)
            #pragma unroll
            for (int q = 0; q < 4; q++) acc[m][nt][q] = 0.f;

    // per-thread invariant fragment addresses
    const uint32_t aRow = sb + SM_A + (uint32_t)(wm * 32 + (lane & 15)) * 144u
                        + ((lane & 16) ? 16u : 0u);
    const uint32_t bRow = sb + SM_B
                        + (uint32_t)(wn * 64 + (lane & 7) + ((lane >> 4) & 1) * 8) * 80u
                        + (uint32_t)((lane >> 3) & 1) * 16u;

    // prologue: chunk 0
    stage_w2(0, 0);
    CP_COMMIT();
    compute_h(0, 0);

    for (int c = 0; c < 16; c++) {
        int buf = c & 1;
        if (c < 15) {
            stage_w2(c + 1, 1 - buf);
            CP_COMMIT();
            compute_h(c + 1, 1 - buf);
            CP_WAIT1();
        } else {
            CP_WAIT0();
        }
        __syncthreads();

        // ---- fp16 split mma over chunk c: 6 eff k16-steps
        #pragma unroll
        for (int ks = 0; ks < 6; ks++) {
            uint32_t aoff = (uint32_t)buf * ABUF_BYTES
                          + ((ks < 4) ? 0u : 64u) + (uint32_t)(ks & 1) * 32u;
            uint32_t a[2][4];
            LDSM_X4(a[0][0], a[0][1], a[0][2], a[0][3], aRow + aoff);
            LDSM_X4(a[1][0], a[1][1], a[1][2], a[1][3], aRow + aoff + 16u * 144u);
            uint32_t boff = (uint32_t)buf * BBUF_BYTES
                          + ((ks == 2 || ks == 3) ? (uint32_t)BREG_BYTES : 0u)
                          + (uint32_t)(ks & 1) * 32u;
            uint32_t bbase = bRow + boff;
            #pragma unroll
            for (int ntp = 0; ntp < 4; ntp++) {
                uint32_t b0, b1, b2, b3;
                LDSM_X4(b0, b1, b2, b3, bbase + (uint32_t)ntp * 1280u);
                MMA_F16(acc[0][2 * ntp],     a[0], b0, b1);
                MMA_F16(acc[1][2 * ntp],     a[1], b0, b1);
                MMA_F16(acc[0][2 * ntp + 1], a[0], b2, b3);
                MMA_F16(acc[1][2 * ntp + 1], a[1], b2, b3);
            }
        }

        // ---- epilogue for this k-component after its last chunk
        if ((c & 7) == 7) {
            int k = c >> 3;
            float colsum[16];
            #pragma unroll
            for (int i = 0; i < 16; i++) colsum[i] = 0.f;
            #pragma unroll
            for (int m = 0; m < 2; m++) {
                int rbase = wm * 32 + m * 16 + group;
                float ew0 = s[SM_EW / 4 + rbase * 2 + k];
                float ew1 = s[SM_EW / 4 + (rbase + 8) * 2 + k];
                #pragma unroll
                for (int nt = 0; nt < 8; nt++) {
                    int col0 = nh * 128 + wn * 64 + nt * 8 + tid4 * 2;
                    float bz0 = s[SM_B2 / 4 + k * 256 + col0];
                    float bz1 = s[SM_B2 / 4 + k * 256 + col0 + 1];
                    colsum[nt * 2 + 0] += fmaxf(acc[m][nt][0] + bz0, 0.f) * ew0
                                        + fmaxf(acc[m][nt][2] + bz0, 0.f) * ew1;
                    colsum[nt * 2 + 1] += fmaxf(acc[m][nt][1] + bz1, 0.f) * ew0
                                        + fmaxf(acc[m][nt][3] + bz1, 0.f) * ew1;
                }
            }
            #pragma unroll
            for (int off = 4; off <= 16; off <<= 1)
                #pragma unroll
                for (int i = 0; i < 16; i++)
                    colsum[i] += __shfl_xor_sync(0xffffffffu, colsum[i], off);
            if (lane < 4) {
                float* dst = s + SM_PART / 4 + (k * 4 + wm) * 128 + wn * 64;
                #pragma unroll
                for (int nt = 0; nt < 8; nt++) {
                    dst[nt * 8 + lane * 2 + 0] = colsum[nt * 2 + 0];
                    dst[nt * 8 + lane * 2 + 1] = colsum[nt * 2 + 1];
                }
            }
            #pragma unroll
            for (int m = 0; m < 2; m++)
                #pragma unroll
                for (int nt = 0; nt < 8; nt++)
                    #pragma unroll
                    for (int q = 0; q < 4; q++) acc[m][nt][q] = 0.f;
        }
        __syncthreads();
    }

    // ---- final aggregation across k and M-warps (2 receivers x 128 cols)
    {
        const float* p = s + SM_PART / 4;
        int recv = t >> 7, col = t & 127;
        float v = p[(recv * 2 + 0) * 128 + col] + p[(recv * 2 + 1) * 128 + col]
                + p[(4 + recv * 2 + 0) * 128 + col] + p[(4 + recv * 2 + 1) * 128 + col];
        g_agg[(b * NN + n0 + recv) * 256 + nh * 128 + col] = v;
    }
}

// ---------------- node kernel: output MLP + RK4, pipelined weight prefetch -----
#define NROWS 16
__global__ __launch_bounds__(256) void node_kernel(
    const float* __restrict__ Wo1, const float* __restrict__ bo1,
    const float* __restrict__ Wo2, const float* __restrict__ bo2,
    const float* __restrict__ Wo3, const float* __restrict__ bo3,
    float* __restrict__ outp, int stage, int step)
{
    __shared__ float s_a[NROWS][264];   // aug, later reused as h2
    __shared__ float s_h[NROWS][264];

    int r0 = blockIdx.x * NROWS;
    int t = threadIdx.x;

    for (int i = t; i < NROWS * 264; i += 256) {
        int r = i / 264, c = i % 264;
        int row = r0 + r;
        float v = 0.f;
        if (c < 4) v = g_xarg[row * 4 + c];
        else if (c < 260) v = g_agg[row * 256 + (c - 4)];
        s_a[r][c] = v;
    }
    __syncthreads();

    float acc[NROWS];
    float w0[8], w1[8];

    // ---- layer 1: K=260 (32 blocks of 8 + tail 4), depth-2 prefetch
    {
        float bv = bo1[t];
        #pragma unroll
        for (int r = 0; r < NROWS; r++) acc[r] = bv;
    }
    #pragma unroll
    for (int q = 0; q < 8; q++) w0[q] = __ldg(&Wo1[q * 256 + t]);
    #pragma unroll
    for (int q = 0; q < 8; q++) w1[q] = __ldg(&Wo1[(8 + q) * 256 + t]);
    #pragma unroll 2
    for (int it = 0; it < 32; it++) {
        int j = it * 8;
        float c[8];
        if ((it & 1) == 0) {
            #pragma unroll
            for (int q = 0; q < 8; q++) c[q] = w0[q];
            int jn = j + 16;
            #pragma unroll
            for (int q = 0; q < 8; q++)
                if (jn + q < 260) w0[q] = __ldg(&Wo1[(jn + q) * 256 + t]);
        } else {
            #pragma unroll
            for (int q = 0; q < 8; q++) c[q] = w1[q];
            int jn = j + 16;
            #pragma unroll
            for (int q = 0; q < 8; q++)
                if (jn + q < 260) w1[q] = __ldg(&Wo1[(jn + q) * 256 + t]);
        }
        #pragma unroll
        for (int r = 0; r < NROWS; r++) {
            float4 a0 = *(const float4*)&s_a[r][j];
            float4 a1 = *(const float4*)&s_a[r][j + 4];
            acc[r] += a0.x * c[0] + a0.y * c[1] + a0.z * c[2] + a0.w * c[3]
                    + a1.x * c[4] + a1.y * c[5] + a1.z * c[6] + a1.w * c[7];
        }
    }
    // tail cols 256..259 live in w0[0..3] (prefetched at it=30)
    #pragma unroll
    for (int r = 0; r < NROWS; r++) {
        float4 a0 = *(const float4*)&s_a[r][256];
        acc[r] += a0.x * w0[0] + a0.y * w0[1] + a0.z * w0[2] + a0.w * w0[3];
    }
    #pragma unroll
    for (int r = 0; r < NROWS; r++) s_h[r][t] = fmaxf(acc[r], 0.f);
    __syncthreads();

    // ---- layer 2: K=256 (32 blocks of 8), depth-2 prefetch
    {
        float bv = bo2[t];
        #pragma unroll
        for (int r = 0; r < NROWS; r++) acc[r] = bv;
    }
    #pragma unroll
    for (int q = 0; q < 8; q++) w0[q] = __ldg(&Wo2[q * 256 + t]);
    #pragma unroll
    for (int q = 0; q < 8; q++) w1[q] = __ldg(&Wo2[(8 + q) * 256 + t]);
    #pragma unroll 2
    for (int it = 0; it < 32; it++) {
        int j = it * 8;
        float c[8];
        if ((it & 1) == 0) {
            #pragma unroll
            for (int q = 0; q < 8; q++) c[q] = w0[q];
            int jn = j + 16;
            #pragma unroll
            for (int q = 0; q < 8; q++)
                if (jn + q < 256) w0[q] = __ldg(&Wo2[(jn + q) * 256 + t]);
        } else {
            #pragma unroll
            for (int q = 0; q < 8; q++) c[q] = w1[q];
            int jn = j + 16;
            #pragma unroll
            for (int q = 0; q < 8; q++)
                if (jn + q < 256) w1[q] = __ldg(&Wo2[(jn + q) * 256 + t]);
        }
        #pragma unroll
        for (int r = 0; r < NROWS; r++) {
            float4 a0 = *(const float4*)&s_h[r][j];
            float4 a1 = *(const float4*)&s_h[r][j + 4];
            acc[r] += a0.x * c[0] + a0.y * c[1] + a0.z * c[2] + a0.w * c[3]
                    + a1.x * c[4] + a1.y * c[5] + a1.z * c[6] + a1.w * c[7];
        }
    }
    __syncthreads();
    #pragma unroll
    for (int r = 0; r < NROWS; r++) s_a[r][t] = fmaxf(acc[r], 0.f);   // h2
    __syncthreads();

    // final 256->4 projection: warp w handles rows 2w, 2w+1
    int wr = t >> 5, lane = t & 31;
    #pragma unroll
    for (int rr = 0; rr < 2; rr++) {
        int rl = wr * 2 + rr;
        float4 pf = make_float4(0.f, 0.f, 0.f, 0.f);
        for (int j = lane; j < 256; j += 32) {
            float v = s_a[rl][j];
            float4 w3 = *(const float4*)(Wo3 + j * 4);
            pf.x += v * w3.x; pf.y += v * w3.y;
            pf.z += v * w3.z; pf.w += v * w3.w;
        }
        #pragma unroll
        for (int off = 16; off; off >>= 1) {
            pf.x += __shfl_xor_sync(0xffffffffu, pf.x, off);
            pf.y += __shfl_xor_sync(0xffffffffu, pf.y, off);
            pf.z += __shfl_xor_sync(0xffffffffu, pf.z, off);
            pf.w += __shfl_xor_sync(0xffffffffu, pf.w, off);
        }

        if (lane == 0) {
            int row = r0 + rl;
            float dt = (float)(step + 1) / 10.0f - (float)step / 10.0f;

            float4 xa = *(const float4*)(g_xarg + row * 4);
            float4 xs = *(const float4*)(g_xst + row * 4);

            float4 ko;
            ko.x = xa.x + pf.x + bo3[0];
            ko.y = xa.y + pf.y + bo3[1];
            ko.z = xa.z + pf.z + bo3[2];
            ko.w = xa.w + pf.w + bo3[3];

            float4 ka;
            if (stage == 0) {
                ka = ko;
            } else {
                ka = *(const float4*)(g_kacc + row * 4);
                float sc = (stage == 3) ? 1.0f : 2.0f;
                ka.x += sc * ko.x; ka.y += sc * ko.y;
                ka.z += sc * ko.z; ka.w += sc * ko.w;
            }

            if (stage < 3) {
                *(float4*)(g_kacc + row * 4) = ka;
                float cc = (stage == 2) ? dt : 0.5f * dt;
                float4 xn;
                xn.x = xs.x + cc * ko.x; xn.y = xs.y + cc * ko.y;
                xn.z = xs.z + cc * ko.z; xn.w = xs.w + cc * ko.w;
                *(float4*)(g_xarg + row * 4) = xn;
            } else {
                float cc = dt * (1.0f / 6.0f);
                float4 xn;
                xn.x = xs.x + cc * ka.x; xn.y = xs.y + cc * ka.y;
                xn.z = xs.z + cc * ka.z; xn.w = xs.w + cc * ka.w;
                *(float4*)(g_xst + row * 4) = xn;
                *(float4*)(g_xarg + row * 4) = xn;
                *(float4*)(outp + (row * NSTEP + step) * 4) = xn;
            }
        }
    }
}

// ---------------- launch ------------------------------------------------------
extern "C" void kernel_launch(void* const* d_in, const int* in_sizes, int n_in,
                              void* d_out, int out_size)
{
    const float* inputs = (const float*)d_in[0];
    const float* edges  = (const float*)d_in[1];
    const float* W1  = (const float*)d_in[4];
    const float* b1  = (const float*)d_in[5];
    const float* W2  = (const float*)d_in[6];
    const float* b2  = (const float*)d_in[7];
    const float* Wo1 = (const float*)d_in[8];
    const float* bo1 = (const float*)d_in[9];
    const float* Wo2 = (const float*)d_in[10];
    const float* bo2 = (const float*)d_in[11];
    const float* Wo3 = (const float*)d_in[12];
    const float* bo3 = (const float*)d_in[13];
    float* outp = (float*)d_out;

    cudaFuncSetAttribute(edge_mma_kernel,
                         cudaFuncAttributeMaxDynamicSharedMemorySize, SMEM_TOT);

    init_kernel<<<(BB * NN * FI + 255) / 256, 256>>>(inputs);
    w2split_kernel<<<(2 * 256 * 256) / 256, 256>>>(W2);

    for (int step = 0; step < NSTEP; step++) {
        for (int stage = 0; stage < 4; stage++) {
            edge_mma_kernel<<<BB * 64, 256, SMEM_TOT>>>(edges, W1, b1, b2);
            node_kernel<<<BB * NN / NROWS, 256>>>(Wo1, bo1, Wo2, bo2, Wo3, bo3,
                                                  outp, stage, step);
        }
    }
}